// round 1
// baseline (speedup 1.0000x reference)
#include <cuda_runtime.h>
#include <math.h>

// Problem constants
#define MODEL_DIM 1024
#define NUM_HEADS 16
#define HEAD_DIM  64
#define WINDOW    32
#define EPS       1e-5f
#define BATCH     2
#define SEQ       2048
#define MROWS     (BATCH * SEQ)       // 4096
#define QKV_LD    (3 * MODEL_DIM)     // 3072

// -------- scratch (static __device__, no allocations) --------
__device__ float g_H  [MROWS * MODEL_DIM];   // normalized activations
__device__ float g_QKV[MROWS * QKV_LD];      // q | k | v
__device__ float g_ATT[MROWS * MODEL_DIM];   // attention output

// ============================================================
// LayerNorm: one block per row (256 threads, 4 floats each)
// ============================================================
__global__ __launch_bounds__(256)
void ln_kernel(const float* __restrict__ x,
               const float* __restrict__ gamma,
               const float* __restrict__ beta,
               float* __restrict__ H)
{
    int row = blockIdx.x;
    int tid = threadIdx.x;
    const float4* xr = (const float4*)(x + (size_t)row * MODEL_DIM);
    float4 a = xr[tid];

    __shared__ float red[8];
    __shared__ float stat;

    // mean
    float s = a.x + a.y + a.z + a.w;
    #pragma unroll
    for (int o = 16; o; o >>= 1) s += __shfl_xor_sync(0xffffffffu, s, o);
    if ((tid & 31) == 0) red[tid >> 5] = s;
    __syncthreads();
    if (tid == 0) {
        float t = 0.f;
        #pragma unroll
        for (int i = 0; i < 8; i++) t += red[i];
        stat = t * (1.0f / MODEL_DIM);
    }
    __syncthreads();
    float mu = stat;

    // variance
    float dx = a.x - mu, dy = a.y - mu, dz = a.z - mu, dw = a.w - mu;
    float s2 = dx*dx + dy*dy + dz*dz + dw*dw;
    #pragma unroll
    for (int o = 16; o; o >>= 1) s2 += __shfl_xor_sync(0xffffffffu, s2, o);
    __syncthreads();                      // protect red[] and stat reuse
    if ((tid & 31) == 0) red[tid >> 5] = s2;
    __syncthreads();
    if (tid == 0) {
        float t = 0.f;
        #pragma unroll
        for (int i = 0; i < 8; i++) t += red[i];
        stat = rsqrtf(t * (1.0f / MODEL_DIM) + EPS);
    }
    __syncthreads();
    float rstd = stat;

    float4 g = ((const float4*)gamma)[tid];
    float4 b = ((const float4*)beta)[tid];
    float4 o;
    o.x = dx * rstd * g.x + b.x;
    o.y = dy * rstd * g.y + b.y;
    o.z = dz * rstd * g.z + b.z;
    o.w = dw * rstd * g.w + b.w;
    ((float4*)(H + (size_t)row * MODEL_DIM))[tid] = o;
}

// ============================================================
// SGEMM: C[M,N] = A[M,K] @ B[K,N] + bias (+ residual)
// BM=BN=128, BK=8, 256 threads, 8x8 per thread.
// M=4096, N=1024, K=1024 -- all tile-divisible, no guards.
// ============================================================
#define BM 128
#define BN 128
#define BK 8
#define TM 8
#define TN 8

template<bool RESID>
__global__ __launch_bounds__(256)
void sgemm_kernel(const float* __restrict__ A,
                  const float* __restrict__ Bw,
                  const float* __restrict__ bias,
                  const float* __restrict__ resid,
                  float* __restrict__ C,
                  int K, int ldb, int ldc)
{
    __shared__ float As[BK][BM];
    __shared__ float Bs[BK][BN];

    int tid = threadIdx.x;
    int tx = tid & 15;         // 16 thread-cols
    int ty = tid >> 4;         // 16 thread-rows

    int aRow = tid >> 1;              // 0..127
    int aCol = (tid & 1) * 4;         // 0 or 4
    int bRow = tid >> 5;              // 0..7
    int bCol = (tid & 31) * 4;        // 0..124

    const float* Aptr = A  + (size_t)(blockIdx.y * BM + aRow) * K + aCol;
    const float* Bptr = Bw + (size_t)bRow * ldb + blockIdx.x * BN + bCol;

    float acc[TM][TN];
    #pragma unroll
    for (int i = 0; i < TM; i++)
        #pragma unroll
        for (int j = 0; j < TN; j++) acc[i][j] = 0.f;

    for (int k0 = 0; k0 < K; k0 += BK) {
        float4 a4 = *(const float4*)(Aptr + k0);
        float4 b4 = *(const float4*)(Bptr + (size_t)k0 * ldb);
        As[aCol + 0][aRow] = a4.x;
        As[aCol + 1][aRow] = a4.y;
        As[aCol + 2][aRow] = a4.z;
        As[aCol + 3][aRow] = a4.w;
        *(float4*)&Bs[bRow][bCol] = b4;
        __syncthreads();

        #pragma unroll
        for (int kk = 0; kk < BK; kk++) {
            float ar[TM], br[TN];
            #pragma unroll
            for (int i = 0; i < TM; i++) ar[i] = As[kk][ty * TM + i];
            #pragma unroll
            for (int j = 0; j < TN; j++) br[j] = Bs[kk][tx * TN + j];
            #pragma unroll
            for (int i = 0; i < TM; i++)
                #pragma unroll
                for (int j = 0; j < TN; j++)
                    acc[i][j] = fmaf(ar[i], br[j], acc[i][j]);
        }
        __syncthreads();
    }

    // epilogue: + bias (+ residual), vectorized stores
    #pragma unroll
    for (int i = 0; i < TM; i++) {
        int row = blockIdx.y * BM + ty * TM + i;
        #pragma unroll
        for (int j = 0; j < TN; j += 4) {
            int col = blockIdx.x * BN + tx * TN + j;
            float4 r;
            r.x = acc[i][j + 0] + bias[col + 0];
            r.y = acc[i][j + 1] + bias[col + 1];
            r.z = acc[i][j + 2] + bias[col + 2];
            r.w = acc[i][j + 3] + bias[col + 3];
            if (RESID) {
                const float4 rs = *(const float4*)(resid + (size_t)row * MODEL_DIM + col);
                r.x += rs.x; r.y += rs.y; r.z += rs.z; r.w += rs.w;
            }
            *(float4*)(C + (size_t)row * ldc + col) = r;
        }
    }
}

// ============================================================
// Sliding-window attention.
// Block = (128 queries, 1 head, 1 batch); 128 threads, 1 query/thread.
// K/V window (192 slots x 64 dims) staged in smem, row pad 65 floats
// (65 mod 32 == 1 -> conflict-free strided reads).
// ============================================================
#define QT 128
#define NS (QT + 2 * WINDOW)    // 192
#define KROW 65

__global__ __launch_bounds__(QT)
void attn_kernel(const float* __restrict__ QKV, float* __restrict__ ATT)
{
    extern __shared__ float sm[];
    float* Ks = sm;               // NS * KROW
    float* Vs = sm + NS * KROW;   // NS * KROW

    int qt = blockIdx.x * QT;
    int h  = blockIdx.y;
    int b  = blockIdx.z;
    int t  = threadIdx.x;
    size_t base = (size_t)b * SEQ * QKV_LD;

    // stage K/V window [qt-32, qt+159] (invalid rows -> 0, masked later)
    for (int idx = t; idx < NS * HEAD_DIM; idx += QT) {
        int kk = idx >> 6;
        int d  = idx & 63;
        int j  = qt - WINDOW + kk;
        float kv = 0.f, vv = 0.f;
        if (j >= 0 && j < SEQ) {
            size_t p = base + (size_t)j * QKV_LD + h * HEAD_DIM + d;
            kv = QKV[p + MODEL_DIM];
            vv = QKV[p + 2 * MODEL_DIM];
        }
        Ks[kk * KROW + d] = kv;
        Vs[kk * KROW + d] = vv;
    }
    __syncthreads();

    int s = qt + t;
    const float4* qp4 = (const float4*)(QKV + base + (size_t)s * QKV_LD + h * HEAD_DIM);
    float q[HEAD_DIM];
    #pragma unroll
    for (int i = 0; i < 16; i++) {
        float4 u = qp4[i];
        q[4*i+0] = u.x * 0.125f;   // 1/sqrt(64)
        q[4*i+1] = u.y * 0.125f;
        q[4*i+2] = u.z * 0.125f;
        q[4*i+3] = u.w * 0.125f;
    }

    // scores
    float sc[2 * WINDOW + 1];
    float m = -1e30f;
    for (int w = 0; w < 2 * WINDOW + 1; w++) {
        int j = s - WINDOW + w;
        const float* kr = Ks + (t + w) * KROW;
        float dot = 0.f;
        #pragma unroll
        for (int d = 0; d < HEAD_DIM; d++) dot = fmaf(q[d], kr[d], dot);
        dot = (j >= 0 && j < SEQ) ? dot : -1e30f;
        sc[w] = dot;
        m = fmaxf(m, dot);
    }

    // softmax
    float denom = 0.f;
    for (int w = 0; w < 2 * WINDOW + 1; w++) {
        float e = __expf(sc[w] - m);
        sc[w] = e;
        denom += e;
    }
    float inv = 1.0f / denom;

    // weighted sum of V
    float o[HEAD_DIM];
    #pragma unroll
    for (int d = 0; d < HEAD_DIM; d++) o[d] = 0.f;
    for (int w = 0; w < 2 * WINDOW + 1; w++) {
        float p = sc[w];
        const float* vr = Vs + (t + w) * KROW;
        #pragma unroll
        for (int d = 0; d < HEAD_DIM; d++) o[d] = fmaf(p, vr[d], o[d]);
    }

    float4* op = (float4*)(ATT + (size_t)(b * SEQ + s) * MODEL_DIM + h * HEAD_DIM);
    #pragma unroll
    for (int i = 0; i < 16; i++) {
        float4 u;
        u.x = o[4*i+0] * inv;
        u.y = o[4*i+1] * inv;
        u.z = o[4*i+2] * inv;
        u.w = o[4*i+3] * inv;
        op[i] = u;
    }
}

// ============================================================
// launch
// ============================================================
extern "C" void kernel_launch(void* const* d_in, const int* in_sizes, int n_in,
                              void* d_out, int out_size)
{
    (void)in_sizes; (void)n_in; (void)out_size;
    const float* x     = (const float*)d_in[0];
    const float* w_q   = (const float*)d_in[1];
    const float* b_q   = (const float*)d_in[2];
    const float* w_k   = (const float*)d_in[3];
    const float* b_k   = (const float*)d_in[4];
    const float* w_v   = (const float*)d_in[5];
    const float* b_v   = (const float*)d_in[6];
    const float* w_o   = (const float*)d_in[7];
    const float* b_o   = (const float*)d_in[8];
    const float* gamma = (const float*)d_in[9];
    const float* beta  = (const float*)d_in[10];
    float* out = (float*)d_out;

    void *pH, *pQKV, *pATT;
    cudaGetSymbolAddress(&pH,   g_H);
    cudaGetSymbolAddress(&pQKV, g_QKV);
    cudaGetSymbolAddress(&pATT, g_ATT);
    float* H   = (float*)pH;
    float* QKV = (float*)pQKV;
    float* ATT = (float*)pATT;

    // 1. LayerNorm
    ln_kernel<<<MROWS, 256>>>(x, gamma, beta, H);

    // 2. QKV projections (each N=1024 into strided QKV buffer)
    dim3 gq(MODEL_DIM / BN, MROWS / BM);   // (8, 32)
    sgemm_kernel<false><<<gq, 256>>>(H, w_q, b_q, nullptr, QKV + 0,              MODEL_DIM, MODEL_DIM, QKV_LD);
    sgemm_kernel<false><<<gq, 256>>>(H, w_k, b_k, nullptr, QKV + MODEL_DIM,     MODEL_DIM, MODEL_DIM, QKV_LD);
    sgemm_kernel<false><<<gq, 256>>>(H, w_v, b_v, nullptr, QKV + 2 * MODEL_DIM, MODEL_DIM, MODEL_DIM, QKV_LD);

    // 3. Sliding-window attention
    int smem = NS * KROW * 2 * (int)sizeof(float);   // 99840 B
    static int smem_set = 0;
    cudaFuncSetAttribute(attn_kernel, cudaFuncAttributeMaxDynamicSharedMemorySize, smem);
    (void)smem_set;
    dim3 ga(SEQ / QT, NUM_HEADS, BATCH);   // (16, 16, 2)
    attn_kernel<<<ga, QT, smem>>>(QKV, ATT);

    // 4. Output projection + bias + residual
    sgemm_kernel<true><<<gq, 256>>>(ATT, w_o, b_o, x, out, MODEL_DIM, MODEL_DIM, MODEL_DIM);
}

// round 3
// speedup vs baseline: 1.8876x; 1.8876x over previous
#include <cuda_runtime.h>
#include <cuda_bf16.h>
#include <cstdint>
#include <math.h>

// ---------------- problem constants ----------------
#define MODEL_DIM 1024
#define NUM_HEADS 16
#define HEAD_DIM  64
#define WINDOW    32
#define EPS       1e-5f
#define BATCH     2
#define SEQ       2048
#define MROWS     (BATCH * SEQ)      // 4096
#define QKV_LD    (3 * MODEL_DIM)    // 3072
#define KX        3072               // expanded K: [hi | hi->lo | lo->hi]

// ---------------- scratch ----------------
__device__ __nv_bfloat16 g_Hx  [MROWS * KX];        // LN output, split-expanded
__device__ __nv_bfloat16 g_Wqkv[QKV_LD * KX];       // [q|k|v]^T split-expanded
__device__ __nv_bfloat16 g_Wo  [MODEL_DIM * KX];    // w_o^T split-expanded
__device__ float         g_bqkv[QKV_LD];
__device__ float         g_QKV [MROWS * QKV_LD];    // fp32 q|k|v
__device__ __nv_bfloat16 g_ATTx[MROWS * KX];        // attention out, split-expanded

// ---------------- helpers ----------------
__device__ __forceinline__ uint32_t smem_u32(const void* p) {
    uint32_t a;
    asm("{ .reg .u64 t; cvta.to.shared.u64 t, %1; cvt.u32.u64 %0, t; }" : "=r"(a) : "l"(p));
    return a;
}
__device__ __forceinline__ void cp_async16(uint32_t dst, const void* src) {
    asm volatile("cp.async.cg.shared.global [%0], [%1], 16;" :: "r"(dst), "l"(src) : "memory");
}
__device__ __forceinline__ void cp_commit() {
    asm volatile("cp.async.commit_group;" ::: "memory");
}
template<int N>
__device__ __forceinline__ void cp_wait() {
    asm volatile("cp.async.wait_group %0;" :: "n"(N) : "memory");
}
__device__ __forceinline__ void ldsm_x4(uint32_t& r0, uint32_t& r1, uint32_t& r2, uint32_t& r3, uint32_t a) {
    asm volatile("ldmatrix.sync.aligned.m8n8.x4.shared.b16 {%0,%1,%2,%3}, [%4];"
                 : "=r"(r0), "=r"(r1), "=r"(r2), "=r"(r3) : "r"(a));
}
__device__ __forceinline__ void mma_bf16(float& c0, float& c1, float& c2, float& c3,
                                         uint32_t a0, uint32_t a1, uint32_t a2, uint32_t a3,
                                         uint32_t b0, uint32_t b1) {
    asm volatile("mma.sync.aligned.m16n8k16.row.col.f32.bf16.bf16.f32 "
                 "{%0,%1,%2,%3},{%4,%5,%6,%7},{%8,%9},{%0,%1,%2,%3};"
                 : "+f"(c0), "+f"(c1), "+f"(c2), "+f"(c3)
                 : "r"(a0), "r"(a1), "r"(a2), "r"(a3), "r"(b0), "r"(b1));
}
__device__ __forceinline__ void split_bf(float v, __nv_bfloat16& hi, __nv_bfloat16& lo) {
    hi = __float2bfloat16(v);
    lo = __float2bfloat16(v - __bfloat162float(hi));
}

// ============================================================
// LayerNorm -> split-expanded bf16 row [hi | hi | lo]
// ============================================================
__global__ __launch_bounds__(256)
void ln_kernel(const float* __restrict__ x,
               const float* __restrict__ gamma,
               const float* __restrict__ beta,
               __nv_bfloat16* __restrict__ Hx)
{
    int row = blockIdx.x;
    int tid = threadIdx.x;
    float4 a = ((const float4*)(x + (size_t)row * MODEL_DIM))[tid];

    __shared__ float red[8];
    __shared__ float stat;

    float s = a.x + a.y + a.z + a.w;
    #pragma unroll
    for (int o = 16; o; o >>= 1) s += __shfl_xor_sync(0xffffffffu, s, o);
    if ((tid & 31) == 0) red[tid >> 5] = s;
    __syncthreads();
    if (tid == 0) {
        float t = 0.f;
        #pragma unroll
        for (int i = 0; i < 8; i++) t += red[i];
        stat = t * (1.0f / MODEL_DIM);
    }
    __syncthreads();
    float mu = stat;

    float dx = a.x - mu, dy = a.y - mu, dz = a.z - mu, dw = a.w - mu;
    float s2 = dx*dx + dy*dy + dz*dz + dw*dw;
    #pragma unroll
    for (int o = 16; o; o >>= 1) s2 += __shfl_xor_sync(0xffffffffu, s2, o);
    __syncthreads();
    if ((tid & 31) == 0) red[tid >> 5] = s2;
    __syncthreads();
    if (tid == 0) {
        float t = 0.f;
        #pragma unroll
        for (int i = 0; i < 8; i++) t += red[i];
        stat = rsqrtf(t * (1.0f / MODEL_DIM) + EPS);
    }
    __syncthreads();
    float rstd = stat;

    float4 g = ((const float4*)gamma)[tid];
    float4 b = ((const float4*)beta)[tid];
    float v[4];
    v[0] = dx * rstd * g.x + b.x;
    v[1] = dy * rstd * g.y + b.y;
    v[2] = dz * rstd * g.z + b.z;
    v[3] = dw * rstd * g.w + b.w;

    __nv_bfloat16 hi[4], lo[4];
    #pragma unroll
    for (int i = 0; i < 4; i++) split_bf(v[i], hi[i], lo[i]);

    size_t p = (size_t)row * KX + tid * 4;
    ((__nv_bfloat162*)(Hx + p))[0]        = __nv_bfloat162(hi[0], hi[1]);
    ((__nv_bfloat162*)(Hx + p))[1]        = __nv_bfloat162(hi[2], hi[3]);
    ((__nv_bfloat162*)(Hx + p + 1024))[0] = __nv_bfloat162(hi[0], hi[1]);
    ((__nv_bfloat162*)(Hx + p + 1024))[1] = __nv_bfloat162(hi[2], hi[3]);
    ((__nv_bfloat162*)(Hx + p + 2048))[0] = __nv_bfloat162(lo[0], lo[1]);
    ((__nv_bfloat162*)(Hx + p + 2048))[1] = __nv_bfloat162(lo[2], lo[3]);
}

// ============================================================
// Weight transpose + split-expand: w[K,N] fp32 -> WT'[N, KX] bf16
// segment layout [hi | lo | hi] (pairs with activations [hi | hi | lo])
// ============================================================
__global__ __launch_bounds__(256)
void wconv_kernel(const float* __restrict__ w,
                  __nv_bfloat16* __restrict__ WT)
{
    __shared__ float tile[32][33];
    int tx = threadIdx.x, ty = threadIdx.y;       // (32, 8)
    int bx = blockIdx.x, by = blockIdx.y;
    #pragma unroll
    for (int i = 0; i < 4; i++) {
        int k = by * 32 + ty + i * 8;
        int n = bx * 32 + tx;
        tile[ty + i * 8][tx] = w[(size_t)k * MODEL_DIM + n];
    }
    __syncthreads();
    #pragma unroll
    for (int i = 0; i < 4; i++) {
        int n = bx * 32 + ty + i * 8;
        int k = by * 32 + tx;
        float v = tile[tx][ty + i * 8];
        __nv_bfloat16 hi, lo;
        split_bf(v, hi, lo);
        size_t base = (size_t)n * KX + k;
        WT[base]        = hi;
        WT[base + 1024] = lo;
        WT[base + 2048] = hi;
    }
}

__global__ void bconcat_kernel(const float* __restrict__ bq,
                               const float* __restrict__ bk,
                               const float* __restrict__ bv,
                               float* __restrict__ dst)
{
    int i = blockIdx.x * 256 + threadIdx.x;
    if (i >= QKV_LD) return;
    const float* s = (i < 1024) ? bq : (i < 2048 ? bk : bv);
    dst[i] = s[i & 1023];
}

// ============================================================
// bf16 mma.sync GEMM: C[M,N] = A'[M,KX] @ B'[N,KX]^T + bias (+resid)
// CTA tile 128x128x64, 8 warps (64x32 each), double-buffered cp.async,
// SW128-swizzled smem, ldmatrix.x4 + mma.sync.m16n8k16.
// ============================================================
#define BM 128
#define BN 128
#define BK 64
#define BKB 128                         // bytes per tile row
#define TILE_BYTES (BM * BKB)           // 16384
#define NIT (KX / BK)                   // 48
#define MM_SMEM (4 * TILE_BYTES)        // 65536 (2 buffers x (A+B))

__device__ __forceinline__ void stage_tile(const __nv_bfloat16* __restrict__ src,
                                           int row0, int k0, uint32_t dst)
{
    int t = threadIdx.x;                 // 256 threads
    int r = t >> 1;                      // 0..127
    int c0 = (t & 1) * 4;                // 16B-chunk base (0 or 4)
    const char* g = (const char*)(src + (size_t)(row0 + r) * KX + k0);
    uint32_t rowoff = dst + r * BKB;
    uint32_t sw = (uint32_t)(r & 7) << 4;
    #pragma unroll
    for (int j = 0; j < 4; j++) {
        uint32_t cb = (uint32_t)(c0 + j) * 16;
        cp_async16(rowoff + (cb ^ sw), g + cb);
    }
}

template<bool RESID>
__global__ __launch_bounds__(256, 2)
void mm_kernel(const __nv_bfloat16* __restrict__ A,
               const __nv_bfloat16* __restrict__ B,
               const float* __restrict__ bias,
               const float* __restrict__ resid,
               float* __restrict__ C, int ldc)
{
    extern __shared__ char smem[];
    uint32_t sb = smem_u32(smem);

    int tid  = threadIdx.x;
    int wid  = tid >> 5;
    int lane = tid & 31;
    int wm = (wid >> 2) * 64;            // warp m offset (0 / 64)
    int wn = (wid & 3) * 32;             // warp n offset (0/32/64/96)
    int rowA = blockIdx.y * BM;
    int rowB = blockIdx.x * BN;

    float acc[4][4][4];
    #pragma unroll
    for (int i = 0; i < 4; i++)
        #pragma unroll
        for (int j = 0; j < 4; j++)
            #pragma unroll
            for (int q = 0; q < 4; q++) acc[i][j][q] = 0.f;

    // per-lane ldmatrix address pieces
    int ra = lane & 15;                          // A row within 16
    uint32_t swa = (uint32_t)(ra & 7) << 4;
    uint32_t ca  = (uint32_t)(lane >> 4) * 16;   // A 16B chunk sel
    int rb = (lane & 7) + ((lane >> 4) & 1) * 8; // B row within 16
    uint32_t swb = (uint32_t)(lane & 7) << 4;
    uint32_t cb  = (uint32_t)((lane >> 3) & 1) * 16;

    // prologue: stage buffer 0
    stage_tile(A, rowA, 0, sb);
    stage_tile(B, rowB, 0, sb + TILE_BYTES);
    cp_commit();

    #pragma unroll 1
    for (int it = 0; it < NIT; it++) {
        int cur = it & 1;
        if (it + 1 < NIT) {
            uint32_t nb = sb + (uint32_t)(1 - cur) * (2 * TILE_BYTES);
            int k0 = (it + 1) * BK;
            stage_tile(A, rowA, k0, nb);
            stage_tile(B, rowB, k0, nb + TILE_BYTES);
            cp_commit();
            cp_wait<1>();
        } else {
            cp_wait<0>();
        }
        __syncthreads();

        uint32_t aB = sb + (uint32_t)cur * (2 * TILE_BYTES);
        uint32_t bB = aB + TILE_BYTES;
        uint32_t aRow[4], bRow[2];
        #pragma unroll
        for (int tm = 0; tm < 4; tm++) aRow[tm] = aB + (uint32_t)(wm + tm * 16 + ra) * BKB;
        #pragma unroll
        for (int tg = 0; tg < 2; tg++) bRow[tg] = bB + (uint32_t)(wn + tg * 16 + rb) * BKB;

        #pragma unroll
        for (int kk = 0; kk < 4; kk++) {
            uint32_t akb = ((uint32_t)kk * 32 + ca) ^ swa;
            uint32_t bkb = ((uint32_t)kk * 32 + cb) ^ swb;
            uint32_t af[4][4];
            uint32_t bf[2][4];
            #pragma unroll
            for (int tm = 0; tm < 4; tm++)
                ldsm_x4(af[tm][0], af[tm][1], af[tm][2], af[tm][3], aRow[tm] + akb);
            #pragma unroll
            for (int tg = 0; tg < 2; tg++)
                ldsm_x4(bf[tg][0], bf[tg][1], bf[tg][2], bf[tg][3], bRow[tg] + bkb);

            #pragma unroll
            for (int tm = 0; tm < 4; tm++)
                #pragma unroll
                for (int tn = 0; tn < 4; tn++) {
                    uint32_t b0 = bf[tn >> 1][(tn & 1) * 2 + 0];
                    uint32_t b1 = bf[tn >> 1][(tn & 1) * 2 + 1];
                    mma_bf16(acc[tm][tn][0], acc[tm][tn][1], acc[tm][tn][2], acc[tm][tn][3],
                             af[tm][0], af[tm][1], af[tm][2], af[tm][3], b0, b1);
                }
        }
        __syncthreads();
    }

    // epilogue
    int mBase = rowA + wm + (lane >> 2);
    int nBase = rowB + wn + (lane & 3) * 2;
    #pragma unroll
    for (int tm = 0; tm < 4; tm++) {
        int m0 = mBase + tm * 16;
        #pragma unroll
        for (int tn = 0; tn < 4; tn++) {
            int n = nBase + tn * 8;
            float bx0 = bias[n], bx1 = bias[n + 1];
            float2 v0, v1;
            v0.x = acc[tm][tn][0] + bx0;
            v0.y = acc[tm][tn][1] + bx1;
            v1.x = acc[tm][tn][2] + bx0;
            v1.y = acc[tm][tn][3] + bx1;
            if (RESID) {
                float2 r0 = *(const float2*)(resid + (size_t)m0 * MODEL_DIM + n);
                float2 r1 = *(const float2*)(resid + (size_t)(m0 + 8) * MODEL_DIM + n);
                v0.x += r0.x; v0.y += r0.y;
                v1.x += r1.x; v1.y += r1.y;
            }
            *(float2*)(C + (size_t)m0 * ldc + n)       = v0;
            *(float2*)(C + (size_t)(m0 + 8) * ldc + n) = v1;
        }
    }
}

// ============================================================
// Sliding-window attention; epilogue writes split-expanded bf16
// ============================================================
#define QT 128
#define NS (QT + 2 * WINDOW)    // 192
#define KROW 65

__global__ __launch_bounds__(QT)
void attn_kernel(const float* __restrict__ QKV,
                 __nv_bfloat16* __restrict__ Ox)
{
    extern __shared__ float sm[];
    float* Ks = sm;
    float* Vs = sm + NS * KROW;

    int qt = blockIdx.x * QT;
    int h  = blockIdx.y;
    int b  = blockIdx.z;
    int t  = threadIdx.x;
    size_t base = (size_t)b * SEQ * QKV_LD;

    for (int idx = t; idx < NS * HEAD_DIM; idx += QT) {
        int kk = idx >> 6;
        int d  = idx & 63;
        int j  = qt - WINDOW + kk;
        float kv = 0.f, vv = 0.f;
        if (j >= 0 && j < SEQ) {
            size_t p = base + (size_t)j * QKV_LD + h * HEAD_DIM + d;
            kv = QKV[p + MODEL_DIM];
            vv = QKV[p + 2 * MODEL_DIM];
        }
        Ks[kk * KROW + d] = kv;
        Vs[kk * KROW + d] = vv;
    }
    __syncthreads();

    int s = qt + t;
    const float4* qp4 = (const float4*)(QKV + base + (size_t)s * QKV_LD + h * HEAD_DIM);
    float q[HEAD_DIM];
    #pragma unroll
    for (int i = 0; i < 16; i++) {
        float4 u = qp4[i];
        q[4*i+0] = u.x * 0.125f;
        q[4*i+1] = u.y * 0.125f;
        q[4*i+2] = u.z * 0.125f;
        q[4*i+3] = u.w * 0.125f;
    }

    float sc[2 * WINDOW + 1];
    float m = -1e30f;
    for (int w = 0; w < 2 * WINDOW + 1; w++) {
        int j = s - WINDOW + w;
        const float* kr = Ks + (t + w) * KROW;
        float dot = 0.f;
        #pragma unroll
        for (int d = 0; d < HEAD_DIM; d++) dot = fmaf(q[d], kr[d], dot);
        dot = (j >= 0 && j < SEQ) ? dot : -1e30f;
        sc[w] = dot;
        m = fmaxf(m, dot);
    }

    float denom = 0.f;
    for (int w = 0; w < 2 * WINDOW + 1; w++) {
        float e = __expf(sc[w] - m);
        sc[w] = e;
        denom += e;
    }
    float inv = 1.0f / denom;

    float o[HEAD_DIM];
    #pragma unroll
    for (int d = 0; d < HEAD_DIM; d++) o[d] = 0.f;
    for (int w = 0; w < 2 * WINDOW + 1; w++) {
        float p = sc[w];
        const float* vr = Vs + (t + w) * KROW;
        #pragma unroll
        for (int d = 0; d < HEAD_DIM; d++) o[d] = fmaf(p, vr[d], o[d]);
    }

    size_t op = (size_t)(b * SEQ + s) * KX + h * HEAD_DIM;
    #pragma unroll
    for (int i = 0; i < 32; i++) {
        float v0 = o[2*i + 0] * inv;
        float v1 = o[2*i + 1] * inv;
        __nv_bfloat16 h0, l0, h1, l1;
        split_bf(v0, h0, l0);
        split_bf(v1, h1, l1);
        __nv_bfloat162 hp(h0, h1), lp(l0, l1);
        ((__nv_bfloat162*)(Ox + op))[i]          = hp;
        ((__nv_bfloat162*)(Ox + op + 1024))[i]   = hp;
        ((__nv_bfloat162*)(Ox + op + 2048))[i]   = lp;
    }
}

// ============================================================
// launch
// ============================================================
extern "C" void kernel_launch(void* const* d_in, const int* in_sizes, int n_in,
                              void* d_out, int out_size)
{
    (void)in_sizes; (void)n_in; (void)out_size;
    const float* x     = (const float*)d_in[0];
    const float* w_q   = (const float*)d_in[1];
    const float* b_q   = (const float*)d_in[2];
    const float* w_k   = (const float*)d_in[3];
    const float* b_k   = (const float*)d_in[4];
    const float* w_v   = (const float*)d_in[5];
    const float* b_v   = (const float*)d_in[6];
    const float* w_o   = (const float*)d_in[7];
    const float* b_o   = (const float*)d_in[8];
    const float* gamma = (const float*)d_in[9];
    const float* beta  = (const float*)d_in[10];
    float* out = (float*)d_out;

    void *pHx, *pWqkv, *pWo, *pBq, *pQKV, *pAx;
    cudaGetSymbolAddress(&pHx,   g_Hx);
    cudaGetSymbolAddress(&pWqkv, g_Wqkv);
    cudaGetSymbolAddress(&pWo,   g_Wo);
    cudaGetSymbolAddress(&pBq,   g_bqkv);
    cudaGetSymbolAddress(&pQKV,  g_QKV);
    cudaGetSymbolAddress(&pAx,   g_ATTx);
    __nv_bfloat16* Hx   = (__nv_bfloat16*)pHx;
    __nv_bfloat16* Wqkv = (__nv_bfloat16*)pWqkv;
    __nv_bfloat16* Wo   = (__nv_bfloat16*)pWo;
    float*         bqkv = (float*)pBq;
    float*         QKV  = (float*)pQKV;
    __nv_bfloat16* ATTx = (__nv_bfloat16*)pAx;

    cudaFuncSetAttribute(mm_kernel<false>, cudaFuncAttributeMaxDynamicSharedMemorySize, MM_SMEM);
    cudaFuncSetAttribute(mm_kernel<true>,  cudaFuncAttributeMaxDynamicSharedMemorySize, MM_SMEM);

    // prep: weights, biases, LN
    dim3 wb(32, 8);
    dim3 wg(32, 32);
    wconv_kernel<<<wg, wb>>>(w_q, Wqkv + (size_t)0 * 1024 * KX);
    wconv_kernel<<<wg, wb>>>(w_k, Wqkv + (size_t)1 * 1024 * KX);
    wconv_kernel<<<wg, wb>>>(w_v, Wqkv + (size_t)2 * 1024 * KX);
    wconv_kernel<<<wg, wb>>>(w_o, Wo);
    bconcat_kernel<<<(QKV_LD + 255) / 256, 256>>>(b_q, b_k, b_v, bqkv);
    ln_kernel<<<MROWS, 256>>>(x, gamma, beta, Hx);

    // fused QKV GEMM: [4096 x 3072]
    dim3 gq(QKV_LD / BN, MROWS / BM);     // (24, 32)
    mm_kernel<false><<<gq, 256, MM_SMEM>>>(Hx, Wqkv, bqkv, nullptr, QKV, QKV_LD);

    // attention
    int asmem = NS * KROW * 2 * (int)sizeof(float);
    cudaFuncSetAttribute(attn_kernel, cudaFuncAttributeMaxDynamicSharedMemorySize, asmem);
    dim3 ga(SEQ / QT, NUM_HEADS, BATCH);
    attn_kernel<<<ga, QT, asmem>>>(QKV, ATTx);

    // output projection + bias + residual
    dim3 go(MODEL_DIM / BN, MROWS / BM);  // (8, 32)
    mm_kernel<true><<<go, 256, MM_SMEM>>>(ATTx, Wo, b_o, x, out, MODEL_DIM);
}

// round 4
// speedup vs baseline: 1.9656x; 1.0413x over previous
#include <cuda_runtime.h>
#include <cuda_bf16.h>
#include <cstdint>
#include <math.h>

// ---------------- problem constants ----------------
#define MODEL_DIM 1024
#define NUM_HEADS 16
#define HEAD_DIM  64
#define WINDOW    32
#define EPS       1e-5f
#define BATCH     2
#define SEQ       2048
#define MROWS     (BATCH * SEQ)      // 4096
#define QKV_LD    (3 * MODEL_DIM)    // 3072
#define KX        3072               // expanded K: [hi | hi | lo] (A) x [hi | lo | hi] (B)

// ---------------- scratch ----------------
__device__ __nv_bfloat16 g_Hx  [MROWS * KX];
__device__ __nv_bfloat16 g_Wqkv[QKV_LD * KX];
__device__ __nv_bfloat16 g_Wo  [MODEL_DIM * KX];
__device__ float         g_bqkv[QKV_LD];
__device__ float         g_QKV [MROWS * QKV_LD];
__device__ __nv_bfloat16 g_ATTx[MROWS * KX];

// ---------------- helpers ----------------
__device__ __forceinline__ uint32_t smem_u32(const void* p) {
    uint32_t a;
    asm("{ .reg .u64 t; cvta.to.shared.u64 t, %1; cvt.u32.u64 %0, t; }" : "=r"(a) : "l"(p));
    return a;
}
__device__ __forceinline__ void cp_async16(uint32_t dst, const void* src) {
    asm volatile("cp.async.cg.shared.global [%0], [%1], 16;" :: "r"(dst), "l"(src) : "memory");
}
__device__ __forceinline__ void cp_commit() {
    asm volatile("cp.async.commit_group;" ::: "memory");
}
template<int N>
__device__ __forceinline__ void cp_wait() {
    asm volatile("cp.async.wait_group %0;" :: "n"(N) : "memory");
}
__device__ __forceinline__ void ldsm_x4(uint32_t& r0, uint32_t& r1, uint32_t& r2, uint32_t& r3, uint32_t a) {
    asm volatile("ldmatrix.sync.aligned.m8n8.x4.shared.b16 {%0,%1,%2,%3}, [%4];"
                 : "=r"(r0), "=r"(r1), "=r"(r2), "=r"(r3) : "r"(a));
}
__device__ __forceinline__ void mma_bf16(float& c0, float& c1, float& c2, float& c3,
                                         uint32_t a0, uint32_t a1, uint32_t a2, uint32_t a3,
                                         uint32_t b0, uint32_t b1) {
    asm volatile("mma.sync.aligned.m16n8k16.row.col.f32.bf16.bf16.f32 "
                 "{%0,%1,%2,%3},{%4,%5,%6,%7},{%8,%9},{%0,%1,%2,%3};"
                 : "+f"(c0), "+f"(c1), "+f"(c2), "+f"(c3)
                 : "r"(a0), "r"(a1), "r"(a2), "r"(a3), "r"(b0), "r"(b1));
}
__device__ __forceinline__ void split_bf(float v, __nv_bfloat16& hi, __nv_bfloat16& lo) {
    hi = __float2bfloat16(v);
    lo = __float2bfloat16(v - __bfloat162float(hi));
}

// ============================================================
// LayerNorm -> split-expanded bf16 row [hi | hi | lo]
// ============================================================
__global__ __launch_bounds__(256)
void ln_kernel(const float* __restrict__ x,
               const float* __restrict__ gamma,
               const float* __restrict__ beta,
               __nv_bfloat16* __restrict__ Hx)
{
    int row = blockIdx.x;
    int tid = threadIdx.x;
    float4 a = ((const float4*)(x + (size_t)row * MODEL_DIM))[tid];

    __shared__ float red[8];
    __shared__ float stat;

    float s = a.x + a.y + a.z + a.w;
    #pragma unroll
    for (int o = 16; o; o >>= 1) s += __shfl_xor_sync(0xffffffffu, s, o);
    if ((tid & 31) == 0) red[tid >> 5] = s;
    __syncthreads();
    if (tid == 0) {
        float t = 0.f;
        #pragma unroll
        for (int i = 0; i < 8; i++) t += red[i];
        stat = t * (1.0f / MODEL_DIM);
    }
    __syncthreads();
    float mu = stat;

    float dx = a.x - mu, dy = a.y - mu, dz = a.z - mu, dw = a.w - mu;
    float s2 = dx*dx + dy*dy + dz*dz + dw*dw;
    #pragma unroll
    for (int o = 16; o; o >>= 1) s2 += __shfl_xor_sync(0xffffffffu, s2, o);
    __syncthreads();
    if ((tid & 31) == 0) red[tid >> 5] = s2;
    __syncthreads();
    if (tid == 0) {
        float t = 0.f;
        #pragma unroll
        for (int i = 0; i < 8; i++) t += red[i];
        stat = rsqrtf(t * (1.0f / MODEL_DIM) + EPS);
    }
    __syncthreads();
    float rstd = stat;

    float4 g = ((const float4*)gamma)[tid];
    float4 b = ((const float4*)beta)[tid];
    float v[4];
    v[0] = dx * rstd * g.x + b.x;
    v[1] = dy * rstd * g.y + b.y;
    v[2] = dz * rstd * g.z + b.z;
    v[3] = dw * rstd * g.w + b.w;

    __nv_bfloat16 hi[4], lo[4];
    #pragma unroll
    for (int i = 0; i < 4; i++) split_bf(v[i], hi[i], lo[i]);

    size_t p = (size_t)row * KX + tid * 4;
    ((__nv_bfloat162*)(Hx + p))[0]        = __nv_bfloat162(hi[0], hi[1]);
    ((__nv_bfloat162*)(Hx + p))[1]        = __nv_bfloat162(hi[2], hi[3]);
    ((__nv_bfloat162*)(Hx + p + 1024))[0] = __nv_bfloat162(hi[0], hi[1]);
    ((__nv_bfloat162*)(Hx + p + 1024))[1] = __nv_bfloat162(hi[2], hi[3]);
    ((__nv_bfloat162*)(Hx + p + 2048))[0] = __nv_bfloat162(lo[0], lo[1]);
    ((__nv_bfloat162*)(Hx + p + 2048))[1] = __nv_bfloat162(lo[2], lo[3]);
}

// ============================================================
// Weight transpose + split-expand, all 4 weights in one launch.
// w[K,N] fp32 -> WT'[N, KX] bf16, segments [hi | lo | hi]
// ============================================================
__global__ __launch_bounds__(256)
void wconv_kernel(const float* __restrict__ wq, const float* __restrict__ wk,
                  const float* __restrict__ wv, const float* __restrict__ wo,
                  __nv_bfloat16* __restrict__ Wqkv, __nv_bfloat16* __restrict__ Wo)
{
    __shared__ float tile[32][33];
    int tx = threadIdx.x, ty = threadIdx.y;       // (32, 8)
    int bx = blockIdx.x, by = blockIdx.y, bz = blockIdx.z;
    const float* w = (bz == 0) ? wq : (bz == 1) ? wk : (bz == 2) ? wv : wo;
    __nv_bfloat16* WT = (bz < 3) ? (Wqkv + (size_t)bz * 1024 * KX) : Wo;

    #pragma unroll
    for (int i = 0; i < 4; i++) {
        int k = by * 32 + ty + i * 8;
        int n = bx * 32 + tx;
        tile[ty + i * 8][tx] = w[(size_t)k * MODEL_DIM + n];
    }
    __syncthreads();
    #pragma unroll
    for (int i = 0; i < 4; i++) {
        int n = bx * 32 + ty + i * 8;
        int k = by * 32 + tx;
        float v = tile[tx][ty + i * 8];
        __nv_bfloat16 hi, lo;
        split_bf(v, hi, lo);
        size_t base = (size_t)n * KX + k;
        WT[base]        = hi;
        WT[base + 1024] = lo;
        WT[base + 2048] = hi;
    }
}

__global__ void bconcat_kernel(const float* __restrict__ bq,
                               const float* __restrict__ bk,
                               const float* __restrict__ bv,
                               float* __restrict__ dst)
{
    int i = blockIdx.x * 256 + threadIdx.x;
    if (i >= QKV_LD) return;
    const float* s = (i < 1024) ? bq : (i < 2048 ? bk : bv);
    dst[i] = s[i & 1023];
}

// ============================================================
// bf16 mma.sync GEMM, 3-stage cp.async pipeline.
// CTA tile 128x128x64, 8 warps (64x32 each).
// ============================================================
#define BM 128
#define BN 128
#define BK 64
#define BKB 128
#define TILE_BYTES (BM * BKB)           // 16384
#define STAGE_BYTES (2 * TILE_BYTES)    // A+B = 32768
#define NSTAGE 3
#define NIT (KX / BK)                   // 48
#define MM_SMEM (NSTAGE * STAGE_BYTES)  // 98304

__device__ __forceinline__ void stage_tile(const __nv_bfloat16* __restrict__ src,
                                           int row0, int k0, uint32_t dst)
{
    int t = threadIdx.x;
    int r = t >> 1;
    int c0 = (t & 1) * 4;
    const char* g = (const char*)(src + (size_t)(row0 + r) * KX + k0);
    uint32_t rowoff = dst + r * BKB;
    uint32_t sw = (uint32_t)(r & 7) << 4;
    #pragma unroll
    for (int j = 0; j < 4; j++) {
        uint32_t cb = (uint32_t)(c0 + j) * 16;
        cp_async16(rowoff + (cb ^ sw), g + cb);
    }
}

template<bool RESID>
__global__ __launch_bounds__(256, 2)
void mm_kernel(const __nv_bfloat16* __restrict__ A,
               const __nv_bfloat16* __restrict__ B,
               const float* __restrict__ bias,
               const float* __restrict__ resid,
               float* __restrict__ C, int ldc)
{
    extern __shared__ char smem[];
    uint32_t sb = smem_u32(smem);

    int tid  = threadIdx.x;
    int wid  = tid >> 5;
    int lane = tid & 31;
    int wm = (wid >> 2) * 64;
    int wn = (wid & 3) * 32;
    int rowA = blockIdx.y * BM;
    int rowB = blockIdx.x * BN;

    float acc[4][4][4];
    #pragma unroll
    for (int i = 0; i < 4; i++)
        #pragma unroll
        for (int j = 0; j < 4; j++)
            #pragma unroll
            for (int q = 0; q < 4; q++) acc[i][j][q] = 0.f;

    int ra = lane & 15;
    uint32_t swa = (uint32_t)(ra & 7) << 4;
    uint32_t ca  = (uint32_t)(lane >> 4) * 16;
    int rb = (lane & 7) + ((lane >> 4) & 1) * 8;
    uint32_t swb = (uint32_t)(lane & 7) << 4;
    uint32_t cb  = (uint32_t)((lane >> 3) & 1) * 16;

    // prologue: stage first 2 K-slabs
    stage_tile(A, rowA, 0, sb);
    stage_tile(B, rowB, 0, sb + TILE_BYTES);
    cp_commit();
    stage_tile(A, rowA, BK, sb + STAGE_BYTES);
    stage_tile(B, rowB, BK, sb + STAGE_BYTES + TILE_BYTES);
    cp_commit();

    #pragma unroll 1
    for (int it = 0; it < NIT; it++) {
        if (it + 1 < NIT) cp_wait<1>(); else cp_wait<0>();
        __syncthreads();

        // prefetch slab it+2 into the stage freed at it-1
        if (it + 2 < NIT) {
            uint32_t nb = sb + (uint32_t)((it + 2) % NSTAGE) * STAGE_BYTES;
            int k0 = (it + 2) * BK;
            stage_tile(A, rowA, k0, nb);
            stage_tile(B, rowB, k0, nb + TILE_BYTES);
            cp_commit();
        }

        uint32_t aB = sb + (uint32_t)(it % NSTAGE) * STAGE_BYTES;
        uint32_t bB = aB + TILE_BYTES;
        uint32_t aRow[4], bRow[2];
        #pragma unroll
        for (int tm = 0; tm < 4; tm++) aRow[tm] = aB + (uint32_t)(wm + tm * 16 + ra) * BKB;
        #pragma unroll
        for (int tg = 0; tg < 2; tg++) bRow[tg] = bB + (uint32_t)(wn + tg * 16 + rb) * BKB;

        #pragma unroll
        for (int kk = 0; kk < 4; kk++) {
            uint32_t akb = ((uint32_t)kk * 32 + ca) ^ swa;
            uint32_t bkb = ((uint32_t)kk * 32 + cb) ^ swb;
            uint32_t af[4][4];
            uint32_t bf[2][4];
            #pragma unroll
            for (int tm = 0; tm < 4; tm++)
                ldsm_x4(af[tm][0], af[tm][1], af[tm][2], af[tm][3], aRow[tm] + akb);
            #pragma unroll
            for (int tg = 0; tg < 2; tg++)
                ldsm_x4(bf[tg][0], bf[tg][1], bf[tg][2], bf[tg][3], bRow[tg] + bkb);

            #pragma unroll
            for (int tm = 0; tm < 4; tm++)
                #pragma unroll
                for (int tn = 0; tn < 4; tn++) {
                    uint32_t b0 = bf[tn >> 1][(tn & 1) * 2 + 0];
                    uint32_t b1 = bf[tn >> 1][(tn & 1) * 2 + 1];
                    mma_bf16(acc[tm][tn][0], acc[tm][tn][1], acc[tm][tn][2], acc[tm][tn][3],
                             af[tm][0], af[tm][1], af[tm][2], af[tm][3], b0, b1);
                }
        }
        __syncthreads();
    }

    int mBase = rowA + wm + (lane >> 2);
    int nBase = rowB + wn + (lane & 3) * 2;
    #pragma unroll
    for (int tm = 0; tm < 4; tm++) {
        int m0 = mBase + tm * 16;
        #pragma unroll
        for (int tn = 0; tn < 4; tn++) {
            int n = nBase + tn * 8;
            float bx0 = bias[n], bx1 = bias[n + 1];
            float2 v0, v1;
            v0.x = acc[tm][tn][0] + bx0;
            v0.y = acc[tm][tn][1] + bx1;
            v1.x = acc[tm][tn][2] + bx0;
            v1.y = acc[tm][tn][3] + bx1;
            if (RESID) {
                float2 r0 = *(const float2*)(resid + (size_t)m0 * MODEL_DIM + n);
                float2 r1 = *(const float2*)(resid + (size_t)(m0 + 8) * MODEL_DIM + n);
                v0.x += r0.x; v0.y += r0.y;
                v1.x += r1.x; v1.y += r1.y;
            }
            *(float2*)(C + (size_t)m0 * ldc + n)       = v0;
            *(float2*)(C + (size_t)(m0 + 8) * ldc + n) = v1;
        }
    }
}

// ============================================================
// Sliding-window attention.
// KROW = 68 floats (272B): 16B-aligned rows, conflict-free LDS.128.
// ============================================================
#define QT 128
#define NS (QT + 2 * WINDOW)    // 192
#define KROW 68
#define ATT_SMEM (2 * NS * KROW * 4)   // 104448

__global__ __launch_bounds__(QT)
void attn_kernel(const float* __restrict__ QKV,
                 __nv_bfloat16* __restrict__ Ox)
{
    extern __shared__ float sm[];
    float* Ks = sm;
    float* Vs = sm + NS * KROW;

    int qt = blockIdx.x * QT;
    int h  = blockIdx.y;
    int b  = blockIdx.z;
    int t  = threadIdx.x;
    size_t base = (size_t)b * SEQ * QKV_LD;

    // stage K/V window as float4 (NS rows x 16 float4)
    for (int idx = t; idx < NS * 16; idx += QT) {
        int kk = idx >> 4;
        int c  = idx & 15;
        int j  = qt - WINDOW + kk;
        float4 kv = make_float4(0.f, 0.f, 0.f, 0.f);
        float4 vv = kv;
        if (j >= 0 && j < SEQ) {
            const float* p = QKV + base + (size_t)j * QKV_LD + h * HEAD_DIM + c * 4;
            kv = *(const float4*)(p + MODEL_DIM);
            vv = *(const float4*)(p + 2 * MODEL_DIM);
        }
        *(float4*)(Ks + kk * KROW + c * 4) = kv;
        *(float4*)(Vs + kk * KROW + c * 4) = vv;
    }
    __syncthreads();

    int s = qt + t;
    const float4* qp4 = (const float4*)(QKV + base + (size_t)s * QKV_LD + h * HEAD_DIM);
    float q[HEAD_DIM];
    #pragma unroll
    for (int i = 0; i < 16; i++) {
        float4 u = qp4[i];
        q[4*i+0] = u.x * 0.125f;
        q[4*i+1] = u.y * 0.125f;
        q[4*i+2] = u.z * 0.125f;
        q[4*i+3] = u.w * 0.125f;
    }

    float sc[2 * WINDOW + 1];
    float m = -1e30f;
    #pragma unroll 1
    for (int w = 0; w < 2 * WINDOW + 1; w++) {
        int j = s - WINDOW + w;
        const float4* kr4 = (const float4*)(Ks + (t + w) * KROW);
        float dot = 0.f;
        #pragma unroll
        for (int i = 0; i < 16; i++) {
            float4 kv = kr4[i];
            dot = fmaf(q[4*i+0], kv.x, dot);
            dot = fmaf(q[4*i+1], kv.y, dot);
            dot = fmaf(q[4*i+2], kv.z, dot);
            dot = fmaf(q[4*i+3], kv.w, dot);
        }
        dot = (j >= 0 && j < SEQ) ? dot : -1e30f;
        sc[w] = dot;
        m = fmaxf(m, dot);
    }

    float denom = 0.f;
    #pragma unroll
    for (int w = 0; w < 2 * WINDOW + 1; w++) {
        float e = __expf(sc[w] - m);
        sc[w] = e;
        denom += e;
    }
    float inv = 1.0f / denom;

    float o[HEAD_DIM];
    #pragma unroll
    for (int d = 0; d < HEAD_DIM; d++) o[d] = 0.f;
    #pragma unroll 1
    for (int w = 0; w < 2 * WINDOW + 1; w++) {
        float p = sc[w];
        const float4* vr4 = (const float4*)(Vs + (t + w) * KROW);
        #pragma unroll
        for (int i = 0; i < 16; i++) {
            float4 vv = vr4[i];
            o[4*i+0] = fmaf(p, vv.x, o[4*i+0]);
            o[4*i+1] = fmaf(p, vv.y, o[4*i+1]);
            o[4*i+2] = fmaf(p, vv.z, o[4*i+2]);
            o[4*i+3] = fmaf(p, vv.w, o[4*i+3]);
        }
    }

    size_t op = (size_t)(b * SEQ + s) * KX + h * HEAD_DIM;
    #pragma unroll
    for (int i = 0; i < 32; i++) {
        float v0 = o[2*i + 0] * inv;
        float v1 = o[2*i + 1] * inv;
        __nv_bfloat16 h0, l0, h1, l1;
        split_bf(v0, h0, l0);
        split_bf(v1, h1, l1);
        __nv_bfloat162 hp(h0, h1), lp(l0, l1);
        ((__nv_bfloat162*)(Ox + op))[i]          = hp;
        ((__nv_bfloat162*)(Ox + op + 1024))[i]   = hp;
        ((__nv_bfloat162*)(Ox + op + 2048))[i]   = lp;
    }
}

// ============================================================
// launch
// ============================================================
extern "C" void kernel_launch(void* const* d_in, const int* in_sizes, int n_in,
                              void* d_out, int out_size)
{
    (void)in_sizes; (void)n_in; (void)out_size;
    const float* x     = (const float*)d_in[0];
    const float* w_q   = (const float*)d_in[1];
    const float* b_q   = (const float*)d_in[2];
    const float* w_k   = (const float*)d_in[3];
    const float* b_k   = (const float*)d_in[4];
    const float* w_v   = (const float*)d_in[5];
    const float* b_v   = (const float*)d_in[6];
    const float* w_o   = (const float*)d_in[7];
    const float* b_o   = (const float*)d_in[8];
    const float* gamma = (const float*)d_in[9];
    const float* beta  = (const float*)d_in[10];
    float* out = (float*)d_out;

    void *pHx, *pWqkv, *pWo, *pBq, *pQKV, *pAx;
    cudaGetSymbolAddress(&pHx,   g_Hx);
    cudaGetSymbolAddress(&pWqkv, g_Wqkv);
    cudaGetSymbolAddress(&pWo,   g_Wo);
    cudaGetSymbolAddress(&pBq,   g_bqkv);
    cudaGetSymbolAddress(&pQKV,  g_QKV);
    cudaGetSymbolAddress(&pAx,   g_ATTx);
    __nv_bfloat16* Hx   = (__nv_bfloat16*)pHx;
    __nv_bfloat16* Wqkv = (__nv_bfloat16*)pWqkv;
    __nv_bfloat16* Wo   = (__nv_bfloat16*)pWo;
    float*         bqkv = (float*)pBq;
    float*         QKV  = (float*)pQKV;
    __nv_bfloat16* ATTx = (__nv_bfloat16*)pAx;

    cudaFuncSetAttribute(mm_kernel<false>, cudaFuncAttributeMaxDynamicSharedMemorySize, MM_SMEM);
    cudaFuncSetAttribute(mm_kernel<true>,  cudaFuncAttributeMaxDynamicSharedMemorySize, MM_SMEM);
    cudaFuncSetAttribute(attn_kernel, cudaFuncAttributeMaxDynamicSharedMemorySize, ATT_SMEM);

    // prep
    dim3 wb(32, 8);
    dim3 wg(32, 32, 4);
    wconv_kernel<<<wg, wb>>>(w_q, w_k, w_v, w_o, Wqkv, Wo);
    bconcat_kernel<<<(QKV_LD + 255) / 256, 256>>>(b_q, b_k, b_v, bqkv);
    ln_kernel<<<MROWS, 256>>>(x, gamma, beta, Hx);

    // fused QKV GEMM: [4096 x 3072]
    dim3 gq(QKV_LD / BN, MROWS / BM);     // (24, 32)
    mm_kernel<false><<<gq, 256, MM_SMEM>>>(Hx, Wqkv, bqkv, nullptr, QKV, QKV_LD);

    // attention
    dim3 ga(SEQ / QT, NUM_HEADS, BATCH);
    attn_kernel<<<ga, QT, ATT_SMEM>>>(QKV, ATTx);

    // output projection + bias + residual
    dim3 go(MODEL_DIM / BN, MROWS / BM);  // (8, 32)
    mm_kernel<true><<<go, 256, MM_SMEM>>>(ATTx, Wo, b_o, x, out, MODEL_DIM);
}